// round 3
// baseline (speedup 1.0000x reference)
#include <cuda_runtime.h>

// DecorrelatedReNorm forward collapses algebraically:
//   W @ W_inv == I  =>  out = (X - running_mean) @ running_W
// We further split running_W = I + E and skip E-blocks that are exactly zero
// (detected per launch by a prep kernel), so the identity case is a pure
// bandwidth-bound streaming pass while remaining correct for arbitrary buffers.

#define CFEAT 512
#define TB    64                 // flag tile edge
#define NBT   (CFEAT / TB)       // 8 -> 64 flags

__device__ int                    g_flags[NBT * NBT];  // [cb * NBT + jb], 1 if E-block nonzero
__device__ __align__(16) float    g_rmW[CFEAT];        // running_mean @ running_W

// Prep: blocks [0, NBT*NBT) each test one 64x64 block of (running_W - I) for
// nonzeros; blocks [NBT*NBT, NBT*NBT+2) compute g_rmW (256 threads * 2 = 512 j).
__global__ void __launch_bounds__(256) prep_kernel(const float* __restrict__ rm,
                                                   const float* __restrict__ rW) {
    int b = blockIdx.x;
    if (b < NBT * NBT) {
        int cb = b / NBT, jb = b % NBT;
        int diff = 0;
        for (int t = threadIdx.x; t < TB * TB; t += blockDim.x) {
            int c = cb * TB + (t / TB);
            int j = jb * TB + (t % TB);
            float v  = rW[c * CFEAT + j];
            float id = (c == j) ? 1.0f : 0.0f;
            diff |= (v != id);
        }
        int any = __syncthreads_or(diff);
        if (threadIdx.x == 0) g_flags[b] = any;
    } else {
        int j = (b - NBT * NBT) * 256 + threadIdx.x;
        if (j < CFEAT) {
            float s = 0.0f;
            #pragma unroll 8
            for (int c = 0; c < CFEAT; ++c) s += rm[c] * rW[c * CFEAT + j];
            g_rmW[j] = s;
        }
    }
}

// Main: one float4 of the output per thread.
// Fast path (all E-blocks for this column group zero): out4 = X4 - rmW4.
// Slow path: dense accumulation over flagged 64-row blocks of E.
__global__ void __launch_bounds__(256) apply_kernel(const float* __restrict__ X,
                                                    const float* __restrict__ rW,
                                                    float* __restrict__ out,
                                                    long long nv4) {
    long long idx = (long long)blockIdx.x * 256 + threadIdx.x;
    if (idx >= nv4) return;

    int       j4 = (int)(idx & (CFEAT / 4 - 1));   // 0..127
    long long n  = idx >> 7;                       // row
    int       j  = j4 * 4;
    int       jb = j / TB;

    int fmask = 0;
    #pragma unroll
    for (int cb = 0; cb < NBT; ++cb)
        fmask |= __ldg(&g_flags[cb * NBT + jb]) << cb;

    const float4* Xrow4 = reinterpret_cast<const float4*>(X + n * CFEAT);
    float4 x = __ldg(&Xrow4[j4]);
    float4 r = *reinterpret_cast<const float4*>(&g_rmW[j]);
    float4 o;
    o.x = x.x - r.x;
    o.y = x.y - r.y;
    o.z = x.z - r.z;
    o.w = x.w - r.w;

    if (fmask) {  // general fallback: out += X_row @ E for nonzero E-blocks
        const float* xrow = X + n * CFEAT;
        for (int cb = 0; cb < NBT; ++cb) {
            if (!((fmask >> cb) & 1)) continue;
            #pragma unroll 4
            for (int ci = 0; ci < TB; ++ci) {
                int   c  = cb * TB + ci;
                float xc = xrow[c];
                float4 w = *reinterpret_cast<const float4*>(&rW[c * CFEAT + j]);
                o.x += xc * (w.x - ((c == j + 0) ? 1.0f : 0.0f));
                o.y += xc * (w.y - ((c == j + 1) ? 1.0f : 0.0f));
                o.z += xc * (w.z - ((c == j + 2) ? 1.0f : 0.0f));
                o.w += xc * (w.w - ((c == j + 3) ? 1.0f : 0.0f));
            }
        }
    }

    reinterpret_cast<float4*>(out)[idx] = o;
}

extern "C" void kernel_launch(void* const* d_in, const int* in_sizes, int n_in,
                              void* d_out, int out_size) {
    const float* X  = (const float*)d_in[0];  // [N, 512]
    const float* rm = (const float*)d_in[1];  // [512]
    const float* rW = (const float*)d_in[2];  // [512, 512]
    float* out = (float*)d_out;

    prep_kernel<<<NBT * NBT + 2, 256>>>(rm, rW);

    long long nv4    = (long long)out_size / 4;            // float4 count
    int       blocks = (int)((nv4 + 255) / 256);
    apply_kernel<<<blocks, 256>>>(X, rW, out, nv4);
}

// round 4
// speedup vs baseline: 1.1808x; 1.1808x over previous
#include <cuda_runtime.h>

// DecorrelatedReNorm forward collapses algebraically:
//   W @ W_inv == I  =>  out = (X - running_mean) @ running_W
// running_W = I + E; a prep pass flags zero 64x64 blocks of E and computes
// rmW = running_mean @ running_W. When E == 0 everywhere (the actual buffer
// init), the apply pass is a pure streaming  out = X - rmW.

#define CFEAT 512
#define TB    64                 // flag tile edge
#define NBT   (CFEAT / TB)       // 8 -> 64 flags
#define NCHUNK 8                 // c-chunks for the rmW partial reduction

__device__ int                 g_flags[NBT * NBT];      // 1 if E-block (cb,jb) nonzero
__device__ int                 g_any;                   // OR of all flags
__device__ __align__(16) float g_partial[NCHUNK][CFEAT];// partial rm@rW sums
__device__ __align__(16) float g_rmW[CFEAT];            // running_mean @ running_W

// Stage 1: blocks [0,64) test one 64x64 block of (rW - I) for nonzeros;
// blocks [64, 64+NCHUNK) compute a 64-row partial of rm @ rW.
__global__ void __launch_bounds__(256) prep_kernel(const float* __restrict__ rm,
                                                   const float* __restrict__ rW) {
    int b = blockIdx.x;
    if (b < NBT * NBT) {
        int cb = b / NBT, jb = b % NBT;
        int diff = 0;
        for (int t = threadIdx.x; t < TB * TB; t += 256) {
            int c = cb * TB + (t / TB);
            int j = jb * TB + (t % TB);
            float v  = rW[c * CFEAT + j];
            float id = (c == j) ? 1.0f : 0.0f;
            diff |= (v != id);
        }
        int any = __syncthreads_or(diff);
        if (threadIdx.x == 0) g_flags[b] = any;
    } else {
        int k  = b - NBT * NBT;              // c-chunk id, 0..7
        int c0 = k * (CFEAT / NCHUNK);       // 64 c's per chunk
        #pragma unroll
        for (int h = 0; h < 2; ++h) {        // j = tid and tid+256
            int j = threadIdx.x + h * 256;
            float s = 0.0f;
            #pragma unroll 8
            for (int ci = 0; ci < CFEAT / NCHUNK; ++ci) {
                int c = c0 + ci;
                s += rm[c] * __ldg(&rW[c * CFEAT + j]);
            }
            g_partial[k][j] = s;
        }
    }
}

// Stage 2 (1 block): fold partials into g_rmW; fold flags into g_any.
__global__ void __launch_bounds__(512) reduce_kernel() {
    int j = threadIdx.x;
    float s = 0.0f;
    #pragma unroll
    for (int k = 0; k < NCHUNK; ++k) s += g_partial[k][j];
    g_rmW[j] = s;

    __shared__ int sh_any;
    if (j == 0) sh_any = 0;
    __syncthreads();
    int f = (j < NBT * NBT) ? g_flags[j] : 0;
    if (__syncthreads_or(f) && j == 0) sh_any = 1;
    __syncthreads();
    if (j == 0) g_any = sh_any;
}

// Stage 3: grid-stride, 4 float4 per thread. Fast path is pure streaming with
// evict-first hints; fallback does the dense X @ E accumulation per element.
__global__ void __launch_bounds__(256) apply_kernel(const float* __restrict__ X,
                                                    const float* __restrict__ rW,
                                                    float* __restrict__ out,
                                                    long long nv4) {
    long long stride = (long long)gridDim.x * 256;
    long long idx0   = (long long)blockIdx.x * 256 + threadIdx.x;
    int any = g_any;   // uniform

    if (!any) {
        const float4* X4 = reinterpret_cast<const float4*>(X);
        float4*       O4 = reinterpret_cast<float4*>(out);
        #pragma unroll 4
        for (long long i = idx0; i < nv4; i += stride) {
            int    j4 = (int)(i & (CFEAT / 4 - 1));
            float4 x  = __ldcs(&X4[i]);
            float4 r  = *reinterpret_cast<const float4*>(&g_rmW[j4 * 4]);
            float4 o;
            o.x = x.x - r.x;  o.y = x.y - r.y;
            o.z = x.z - r.z;  o.w = x.w - r.w;
            __stcs(&O4[i], o);
        }
        return;
    }

    // General fallback: out = (X - rm) @ rW, via out = X - rmW + X @ E
    for (long long i = idx0; i < nv4; i += stride) {
        int       j4 = (int)(i & (CFEAT / 4 - 1));
        long long n  = i >> 7;
        int       j  = j4 * 4;
        int       jb = j / TB;

        const float4* Xrow4 = reinterpret_cast<const float4*>(X + n * CFEAT);
        float4 x = __ldg(&Xrow4[j4]);
        float4 r = *reinterpret_cast<const float4*>(&g_rmW[j]);
        float4 o;
        o.x = x.x - r.x;  o.y = x.y - r.y;
        o.z = x.z - r.z;  o.w = x.w - r.w;

        const float* xrow = X + n * CFEAT;
        #pragma unroll
        for (int cb = 0; cb < NBT; ++cb) {
            if (!__ldg(&g_flags[cb * NBT + jb])) continue;
            #pragma unroll 4
            for (int ci = 0; ci < TB; ++ci) {
                int   c  = cb * TB + ci;
                float xc = xrow[c];
                float4 w = *reinterpret_cast<const float4*>(&rW[c * CFEAT + j]);
                o.x += xc * (w.x - ((c == j + 0) ? 1.0f : 0.0f));
                o.y += xc * (w.y - ((c == j + 1) ? 1.0f : 0.0f));
                o.z += xc * (w.z - ((c == j + 2) ? 1.0f : 0.0f));
                o.w += xc * (w.w - ((c == j + 3) ? 1.0f : 0.0f));
            }
        }
        reinterpret_cast<float4*>(out)[i] = o;
    }
}

extern "C" void kernel_launch(void* const* d_in, const int* in_sizes, int n_in,
                              void* d_out, int out_size) {
    const float* X  = (const float*)d_in[0];  // [N, 512]
    const float* rm = (const float*)d_in[1];  // [512]
    const float* rW = (const float*)d_in[2];  // [512, 512]
    float* out = (float*)d_out;

    prep_kernel<<<NBT * NBT + NCHUNK, 256>>>(rm, rW);
    reduce_kernel<<<1, 512>>>();

    long long nv4 = (long long)out_size / 4;             // 16,777,216 float4
    int blocks    = (int)((nv4 / 4 + 255) / 256);        // 4 float4 per thread
    apply_kernel<<<blocks, 256>>>(X, rW, out, nv4);
}

// round 5
// speedup vs baseline: 1.2147x; 1.0287x over previous
#include <cuda_runtime.h>

// DecorrelatedReNorm forward collapses algebraically:
//   W @ W_inv == I  =>  out = (X - running_mean) @ running_W
// running_W = I + E; prep flags zero 64x64 blocks of E and computes
// rmW = running_mean @ running_W in a single fused read of rW. When E == 0
// (the actual buffer init), apply is a pure stream: out = X - rmW.

#define CFEAT 512
#define TB    64                  // flag tile edge
#define NBT   (CFEAT / TB)        // 8 jb column-blocks
#define PBLK  64                  // prep stage-1 blocks (8 rows of rW each)

__device__ __align__(16) float g_partial[PBLK][CFEAT]; // per-block rm@rW partials
__device__ int                 g_flagpart[PBLK];       // per-block jb bitmask of E!=0
__device__ int                 g_flagmask[NBT];        // per-cb jb bitmask (folded)
__device__ int                 g_any;                  // OR of everything
__device__ __align__(16) float g_rmW[CFEAT];           // running_mean @ running_W

// Stage 1: 64 blocks; block b owns rows c in [8b, 8b+8) of rW. Single float4
// pass computes both the identity-diff flags and the rm-weighted partial sums.
__global__ void __launch_bounds__(256) prep1_kernel(const float* __restrict__ rm,
                                                    const float* __restrict__ rW) {
    int b  = blockIdx.x;
    int t  = threadIdx.x;
    int j4 = t & 127;            // float4 column 0..127
    int g  = t >> 7;             // row-subgroup 0..1
    int c0 = b * 8 + g * 4;
    int j  = j4 * 4;
    int jb = j / TB;

    __shared__ float4 sh[128];
    __shared__ int    shmask;
    if (t == 0) shmask = 0;

    const float4* W4 = reinterpret_cast<const float4*>(rW);
    float4 acc = make_float4(0.f, 0.f, 0.f, 0.f);
    int diff = 0;
    #pragma unroll
    for (int k = 0; k < 4; ++k) {
        int    c   = c0 + k;
        float4 w   = __ldg(&W4[c * (CFEAT / 4) + j4]);
        float  rmc = __ldg(&rm[c]);
        acc.x += rmc * w.x;  acc.y += rmc * w.y;
        acc.z += rmc * w.z;  acc.w += rmc * w.w;
        diff |= (w.x != ((c == j + 0) ? 1.0f : 0.0f));
        diff |= (w.y != ((c == j + 1) ? 1.0f : 0.0f));
        diff |= (w.z != ((c == j + 2) ? 1.0f : 0.0f));
        diff |= (w.w != ((c == j + 3) ? 1.0f : 0.0f));
    }
    __syncthreads();                     // shmask init visible
    if (g == 1) sh[j4] = acc;
    if (diff) atomicOr(&shmask, 1 << jb);  // bitwise OR: order-independent
    __syncthreads();
    if (g == 0) {
        float4 o = sh[j4];
        acc.x += o.x;  acc.y += o.y;  acc.z += o.z;  acc.w += o.w;
        reinterpret_cast<float4*>(g_partial[b])[j4] = acc;
    }
    if (t == 0) g_flagpart[b] = shmask;
}

// Stage 2 (1 block, 512 threads): fold partials + flags. All L2-hot.
__global__ void __launch_bounds__(512) prep2_kernel() {
    int j = threadIdx.x;
    float s = 0.0f;
    #pragma unroll 16
    for (int b = 0; b < PBLK; ++b) s += g_partial[b][j];
    g_rmW[j] = s;

    if (j < NBT) {               // cb = j
        int m = 0;
        #pragma unroll
        for (int b = j * 8; b < j * 8 + 8; ++b) m |= g_flagpart[b];
        g_flagmask[j] = m;
    }
    int f = (j < PBLK) ? g_flagpart[j] : 0;
    int a = __syncthreads_or(f);
    if (j == 0) g_any = (a != 0);
}

// Stage 3: grid-stride, 4 float4 per thread. Fast path is pure streaming with
// evict-first hints; fallback does the dense X @ E accumulation per element.
__global__ void __launch_bounds__(256) apply_kernel(const float* __restrict__ X,
                                                    const float* __restrict__ rW,
                                                    float* __restrict__ out,
                                                    long long nv4) {
    long long stride = (long long)gridDim.x * 256;
    long long idx0   = (long long)blockIdx.x * 256 + threadIdx.x;
    int any = g_any;   // uniform

    if (!any) {
        const float4* X4 = reinterpret_cast<const float4*>(X);
        float4*       O4 = reinterpret_cast<float4*>(out);
        #pragma unroll 4
        for (long long i = idx0; i < nv4; i += stride) {
            int    j4 = (int)(i & (CFEAT / 4 - 1));
            float4 x  = __ldcs(&X4[i]);
            float4 r  = *reinterpret_cast<const float4*>(&g_rmW[j4 * 4]);
            float4 o;
            o.x = x.x - r.x;  o.y = x.y - r.y;
            o.z = x.z - r.z;  o.w = x.w - r.w;
            __stcs(&O4[i], o);
        }
        return;
    }

    // General fallback: out = X - rmW + X @ E over flagged 64-row blocks.
    for (long long i = idx0; i < nv4; i += stride) {
        int       j4 = (int)(i & (CFEAT / 4 - 1));
        long long n  = i >> 7;
        int       j  = j4 * 4;
        int       jb = j / TB;

        const float4* Xrow4 = reinterpret_cast<const float4*>(X + n * CFEAT);
        float4 x = __ldg(&Xrow4[j4]);
        float4 r = *reinterpret_cast<const float4*>(&g_rmW[j]);
        float4 o;
        o.x = x.x - r.x;  o.y = x.y - r.y;
        o.z = x.z - r.z;  o.w = x.w - r.w;

        const float* xrow = X + n * CFEAT;
        #pragma unroll
        for (int cb = 0; cb < NBT; ++cb) {
            if (!((__ldg(&g_flagmask[cb]) >> jb) & 1)) continue;
            #pragma unroll 4
            for (int ci = 0; ci < TB; ++ci) {
                int   c  = cb * TB + ci;
                float xc = xrow[c];
                float4 w = *reinterpret_cast<const float4*>(&rW[c * CFEAT + j]);
                o.x += xc * (w.x - ((c == j + 0) ? 1.0f : 0.0f));
                o.y += xc * (w.y - ((c == j + 1) ? 1.0f : 0.0f));
                o.z += xc * (w.z - ((c == j + 2) ? 1.0f : 0.0f));
                o.w += xc * (w.w - ((c == j + 3) ? 1.0f : 0.0f));
            }
        }
        reinterpret_cast<float4*>(out)[i] = o;
    }
}

extern "C" void kernel_launch(void* const* d_in, const int* in_sizes, int n_in,
                              void* d_out, int out_size) {
    const float* X  = (const float*)d_in[0];  // [N, 512]
    const float* rm = (const float*)d_in[1];  // [512]
    const float* rW = (const float*)d_in[2];  // [512, 512]
    float* out = (float*)d_out;

    prep1_kernel<<<PBLK, 256>>>(rm, rW);
    prep2_kernel<<<1, 512>>>();

    long long nv4 = (long long)out_size / 4;          // 16,777,216 float4
    int blocks    = (int)((nv4 / 4 + 255) / 256);     // 4 float4 per thread
    apply_kernel<<<blocks, 256>>>(X, rW, out, nv4);
}